// round 14
// baseline (speedup 1.0000x reference)
#include <cuda_runtime.h>
#include <cstdint>

// Problem sizes (fixed by reference_code)
#define NN0 500000
#define NN1 100000
#define NN2 25000
#define EE0 1600000
#define EE1 400000
#define DIN 128
#define DH  256
#define DOUT 128
#define MAXDEG 64

// ---------------- device scratch (no allocations allowed) ----------------
__device__ float4 g_agg0[(size_t)NN1 * DIN / 4];   // 51.2 MB
__device__ float4 g_h   [(size_t)NN1 * DH / 4];    // 102.4 MB
__device__ float4 g_agg1[(size_t)NN2 * DH / 4];    // 25.6 MB
__device__ int    g_deg0[NN1];
__device__ int    g_deg1[NN2];
__device__ int4   g_srt0[(size_t)NN1 * MAXDEG / 4];  // 25.6 MB
__device__ int4   g_srt1[(size_t)NN2 * MAXDEG / 4];  // 6.4 MB

// ---------------- zero degree counters ----------------
__global__ void zero_deg_kernel() {
    int i = blockIdx.x * 256 + threadIdx.x;
    if (i < NN1) g_deg0[i] = 0;
    else if (i < NN1 + NN2) g_deg1[i - NN1] = 0;
}

// ---------------- padded-CSR fill ----------------
__global__ void fill0_kernel(const int* __restrict__ es, const int* __restrict__ ed) {
    int e = blockIdx.x * 256 + threadIdx.x;
    if (e >= EE0) return;
    int dst = ed[e];
    int p = atomicAdd(&g_deg0[dst], 1);
    if (p < MAXDEG) ((int*)g_srt0)[(size_t)dst * MAXDEG + p] = es[e];
}
__global__ void fill1_kernel(const int* __restrict__ es, const int* __restrict__ ed) {
    int e = blockIdx.x * 256 + threadIdx.x;
    if (e >= EE1) return;
    int dst = ed[e];
    int p = atomicAdd(&g_deg1[dst], 1);
    if (p < MAXDEG) ((int*)g_srt1)[(size_t)dst * MAXDEG + p] = es[e];
}

// ---------------- gather-reduce aggregation (mean) ----------------
__device__ __forceinline__ void f4add(float4& a, float4 b) {
    a.x += b.x; a.y += b.y; a.z += b.z; a.w += b.w;
}

// hop 0: D=128 -> one warp per dst, float4 per lane. grid = NN1*32/256 exactly.
__global__ __launch_bounds__(256)
void agg0_kernel(const float4* __restrict__ x4) {
    unsigned gt = blockIdx.x * 256u + threadIdx.x;
    int w = gt >> 5;            // dst node
    int lane = gt & 31;
    int n = min(g_deg0[w], MAXDEG);
    const int4* idx4 = &g_srt0[(size_t)w * (MAXDEG / 4)];
    float4 acc = make_float4(0.f, 0.f, 0.f, 0.f);
    int p = 0;
    for (; p + 4 <= n; p += 4) {
        int4 s = __ldg(idx4 + (p >> 2));   // warp-uniform broadcast
        float4 a = __ldg(&x4[(size_t)s.x * 32 + lane]);
        float4 b = __ldg(&x4[(size_t)s.y * 32 + lane]);
        float4 c = __ldg(&x4[(size_t)s.z * 32 + lane]);
        float4 d = __ldg(&x4[(size_t)s.w * 32 + lane]);
        f4add(acc, a); f4add(acc, b); f4add(acc, c); f4add(acc, d);
    }
    if (p < n) {
        int4 s = __ldg(idx4 + (p >> 2));
        const int rem = n - p;
        f4add(acc, __ldg(&x4[(size_t)s.x * 32 + lane]));
        if (rem > 1) f4add(acc, __ldg(&x4[(size_t)s.y * 32 + lane]));
        if (rem > 2) f4add(acc, __ldg(&x4[(size_t)s.z * 32 + lane]));
    }
    float inv = 1.0f / fmaxf((float)n, 1.0f);
    acc.x *= inv; acc.y *= inv; acc.z *= inv; acc.w *= inv;
    g_agg0[(size_t)w * 32 + lane] = acc;
}

// hop 1: D=256 -> one warp per dst, 2x float4 per lane. grid = NN2*32/256 exactly.
__global__ __launch_bounds__(256)
void agg1_kernel() {
    unsigned gt = blockIdx.x * 256u + threadIdx.x;
    int w = gt >> 5;
    int lane = gt & 31;
    int n = min(g_deg1[w], MAXDEG);
    const int4* idx4 = &g_srt1[(size_t)w * (MAXDEG / 4)];
    float4 acc0 = make_float4(0.f, 0.f, 0.f, 0.f);
    float4 acc1 = make_float4(0.f, 0.f, 0.f, 0.f);
    int p = 0;
    for (; p + 2 <= n; p += 2) {
        int2 s = __ldg((const int2*)idx4 + (p >> 1));
        f4add(acc0, g_h[(size_t)s.x * 64 + lane]);
        f4add(acc1, g_h[(size_t)s.x * 64 + 32 + lane]);
        f4add(acc0, g_h[(size_t)s.y * 64 + lane]);
        f4add(acc1, g_h[(size_t)s.y * 64 + 32 + lane]);
    }
    if (p < n) {
        int s = ((const int*)idx4)[p];
        f4add(acc0, g_h[(size_t)s * 64 + lane]);
        f4add(acc1, g_h[(size_t)s * 64 + 32 + lane]);
    }
    float inv = 1.0f / fmaxf((float)n, 1.0f);
    acc0.x *= inv; acc0.y *= inv; acc0.z *= inv; acc0.w *= inv;
    acc1.x *= inv; acc1.y *= inv; acc1.z *= inv; acc1.w *= inv;
    g_agg1[(size_t)w * 64 + lane] = acc0;
    g_agg1[(size_t)w * 64 + 32 + lane] = acc1;
}

// ---------------- tf32 helpers ----------------
__device__ __forceinline__ uint32_t f2tf32(float f) {
    uint32_t r;
    asm("cvt.rna.tf32.f32 %0, %1;" : "=r"(r) : "f"(f));
    return r;
}
__device__ __forceinline__ void mma_tf32(float* c, const uint32_t* a,
                                         const uint32_t* b) {
    asm volatile(
        "mma.sync.aligned.m16n8k8.row.col.f32.tf32.tf32.f32 "
        "{%0,%1,%2,%3}, {%4,%5,%6,%7}, {%8,%9}, {%0,%1,%2,%3};"
        : "+f"(c[0]), "+f"(c[1]), "+f"(c[2]), "+f"(c[3])
        : "r"(a[0]), "r"(a[1]), "r"(a[2]), "r"(a[3]), "r"(b[0]), "r"(b[1]));
}

// ---------------- fused SAGEConv tf32 GEMM (cp.async, 2 CTA/SM) ----------------
// out[m,n] = act( sum_k A0[m,k]*B0[n,k] + sum_k A1[m,k]*B1[n,k] + bias[n] )
// Block tile 128x128, BK=32, 256 threads, warp tile 64x32 (m16n8k8 tf32).
// fp32 staged to SMEM via cp.async.cg (double buffer); cvt.rna at fragment load.
template<int KHALF, int N, int DO_RELU>
__global__ __launch_bounds__(256, 2)
void sage_mma_gemm(const float* __restrict__ A0,
                   const float* __restrict__ A1,
                   const float* __restrict__ B0, const float* __restrict__ B1,
                   const float* __restrict__ bias,
                   float* __restrict__ out, int M) {
    constexpr int BK = 32;
    constexpr int LDS_W = BK + 4;      // (4r+c) mod 32 conflict-free
    constexpr int CH = KHALF / BK;
    constexpr int NC = 2 * CH;

    extern __shared__ float sm[];
    float (*As)[128][LDS_W] = (float (*)[128][LDS_W])sm;
    float (*Bs)[128][LDS_W] = (float (*)[128][LDS_W])(sm + 2 * 128 * LDS_W);

    const int tid = threadIdx.x;
    const int wid = tid >> 5;
    const int lane = tid & 31;
    const int lrow = lane >> 2;
    const int lcol = lane & 3;
    const int warp_m = (wid >> 2) * 64;
    const int warp_n = (wid & 3) * 32;
    const int row0 = blockIdx.x * 128;
    const int col0 = blockIdx.y * 128;

    float acc[4][4][4];
#pragma unroll
    for (int mi = 0; mi < 4; ++mi)
#pragma unroll
        for (int ni = 0; ni < 4; ++ni)
#pragma unroll
            for (int j = 0; j < 4; ++j) acc[mi][ni][j] = 0.f;

    // issue one chunk's A+B tiles as cp.async (8 x 16B per thread)
    auto issue = [&](int c) {
        const float* __restrict__ A = (c < CH) ? A0 : A1;
        const float* __restrict__ B = (c < CH) ? B0 : B1;
        const int kb = ((c < CH) ? c : c - CH) * BK;
        const int buf = c & 1;
#pragma unroll
        for (int t = 0; t < 4; ++t) {
            int i = tid + t * 256;
            int r = i >> 3;
            int c4 = (i & 7) * 4;
            int row = row0 + r;
            int valid = (row < M);
            int rowc = valid ? row : (M - 1);          // safe address
            uint32_t da = (uint32_t)__cvta_generic_to_shared(&As[buf][r][c4]);
            asm volatile("cp.async.cg.shared.global [%0], [%1], 16, %2;"
                         :: "r"(da),
                            "l"(A + (size_t)rowc * KHALF + kb + c4),
                            "r"(valid ? 16 : 0));
            uint32_t db = (uint32_t)__cvta_generic_to_shared(&Bs[buf][r][c4]);
            asm volatile("cp.async.cg.shared.global [%0], [%1], 16;"
                         :: "r"(db),
                            "l"(B + (size_t)(col0 + r) * KHALF + kb + c4));
        }
        asm volatile("cp.async.commit_group;");
    };

    issue(0);

#pragma unroll 1
    for (int c = 0; c < NC; ++c) {
        const int buf = c & 1;
        const bool more = (c + 1 < NC);
        if (more) {
            issue(c + 1);
            asm volatile("cp.async.wait_group 1;");
        } else {
            asm volatile("cp.async.wait_group 0;");
        }
        __syncthreads();
        // --- compute chunk c: 4 k-steps of m16n8k8 ---
#pragma unroll
        for (int kk = 0; kk < 4; ++kk) {
            const int kof = kk * 8;
            uint32_t af[4][4], bf[4][2];
#pragma unroll
            for (int mi = 0; mi < 4; ++mi) {
                int m = warp_m + mi * 16 + lrow;
                af[mi][0] = f2tf32(As[buf][m][kof + lcol]);
                af[mi][1] = f2tf32(As[buf][m + 8][kof + lcol]);
                af[mi][2] = f2tf32(As[buf][m][kof + lcol + 4]);
                af[mi][3] = f2tf32(As[buf][m + 8][kof + lcol + 4]);
            }
#pragma unroll
            for (int ni = 0; ni < 4; ++ni) {
                int n = warp_n + ni * 8 + lrow;
                bf[ni][0] = f2tf32(Bs[buf][n][kof + lcol]);
                bf[ni][1] = f2tf32(Bs[buf][n][kof + lcol + 4]);
            }
#pragma unroll
            for (int mi = 0; mi < 4; ++mi)
#pragma unroll
                for (int ni = 0; ni < 4; ++ni)
                    mma_tf32(acc[mi][ni], af[mi], bf[ni]);
        }
        if (more) __syncthreads();   // protect buf before chunk c+2 overwrites
    }

    // --- epilogue: bias + optional relu ---
#pragma unroll
    for (int mi = 0; mi < 4; ++mi) {
        int r_lo = row0 + warp_m + mi * 16 + lrow;
        int r_hi = r_lo + 8;
#pragma unroll
        for (int ni = 0; ni < 4; ++ni) {
            int c = col0 + warp_n + ni * 8 + 2 * lcol;
            float bx = __ldg(bias + c);
            float by = __ldg(bias + c + 1);
            if (r_lo < M) {
                float2 v = make_float2(acc[mi][ni][0] + bx, acc[mi][ni][1] + by);
                if (DO_RELU) { v.x = fmaxf(v.x, 0.f); v.y = fmaxf(v.y, 0.f); }
                *(float2*)(out + (size_t)r_lo * N + c) = v;
            }
            if (r_hi < M) {
                float2 v = make_float2(acc[mi][ni][2] + bx, acc[mi][ni][3] + by);
                if (DO_RELU) { v.x = fmaxf(v.x, 0.f); v.y = fmaxf(v.y, 0.f); }
                *(float2*)(out + (size_t)r_hi * N + c) = v;
            }
        }
    }
}

#define GEMM_SMEM (4 * 128 * 36 * 4)   // 73728 bytes (2 buf x (A+B))

// ---------------- host launcher ----------------
extern "C" void kernel_launch(void* const* d_in, const int* in_sizes, int n_in,
                              void* d_out, int out_size) {
    const float* x   = (const float*)d_in[0];
    const float* Wl0 = (const float*)d_in[1];
    const float* bl0 = (const float*)d_in[2];
    const float* Wr0 = (const float*)d_in[3];
    const float* Wl1 = (const float*)d_in[4];
    const float* bl1 = (const float*)d_in[5];
    const float* Wr1 = (const float*)d_in[6];
    const int* e0s = (const int*)d_in[7];
    const int* e0d = (const int*)d_in[8];
    const int* e1s = (const int*)d_in[9];
    const int* e1d = (const int*)d_in[10];
    float* out = (float*)d_out;

    void *p_agg0, *p_h, *p_agg1;
    cudaGetSymbolAddress(&p_agg0, g_agg0);
    cudaGetSymbolAddress(&p_h,    g_h);
    cudaGetSymbolAddress(&p_agg1, g_agg1);

    cudaFuncSetAttribute(sage_mma_gemm<DIN, DH, 1>,
                         cudaFuncAttributeMaxDynamicSharedMemorySize, GEMM_SMEM);
    cudaFuncSetAttribute(sage_mma_gemm<DH, DOUT, 0>,
                         cudaFuncAttributeMaxDynamicSharedMemorySize, GEMM_SMEM);

    // 1. zero degree counters
    zero_deg_kernel<<<(NN1 + NN2 + 255) / 256, 256>>>();

    // 2. build padded CSR for both hops
    fill0_kernel<<<(EE0 + 255) / 256, 256>>>(e0s, e0d);
    fill1_kernel<<<(EE1 + 255) / 256, 256>>>(e1s, e1d);

    // 3. hop-0 aggregate (mean)
    agg0_kernel<<<NN1 * 32 / 256, 256>>>((const float4*)x);

    // 4. hop-0 dense: h = relu([agg0 | x[:N1]] @ [Wl0|Wr0]^T + b)
    {
        dim3 grid((NN1 + 127) / 128, DH / 128);
        sage_mma_gemm<DIN, DH, 1><<<grid, 256, GEMM_SMEM>>>(
            (const float*)p_agg0, x, Wl0, Wr0, bl0, (float*)p_h, NN1);
    }

    // 5. hop-1 aggregate (mean)
    agg1_kernel<<<NN2 * 32 / 256, 256>>>();

    // 6. hop-1 dense: out = [agg1 | h[:N2]] @ [Wl1|Wr1]^T + b
    {
        dim3 grid((NN2 + 127) / 128, DOUT / 128);
        sage_mma_gemm<DH, DOUT, 0><<<grid, 256, GEMM_SMEM>>>(
            (const float*)p_agg1, (const float*)p_h, Wl1, Wr1, bl1, out, NN2);
    }
    (void)in_sizes; (void)n_in; (void)out_size;
}

// round 15
// speedup vs baseline: 1.0304x; 1.0304x over previous
#include <cuda_runtime.h>
#include <cstdint>

// Problem sizes (fixed by reference_code)
#define NN0 500000
#define NN1 100000
#define NN2 25000
#define EE0 1600000
#define EE1 400000
#define DIN 128
#define DH  256
#define DOUT 128
#define MAXDEG 64

// ---------------- device scratch (no allocations allowed) ----------------
__device__ float4 g_agg0[(size_t)NN1 * DIN / 4];   // 51.2 MB
__device__ float4 g_h   [(size_t)NN1 * DH / 4];    // 102.4 MB
__device__ float4 g_agg1[(size_t)NN2 * DH / 4];    // 25.6 MB
__device__ int    g_deg0[NN1];
__device__ int    g_deg1[NN2];
__device__ int4   g_srt0[(size_t)NN1 * MAXDEG / 4];  // 25.6 MB
__device__ int4   g_srt1[(size_t)NN2 * MAXDEG / 4];  // 6.4 MB

// ---------------- zero degree counters ----------------
__global__ void zero_deg_kernel() {
    int i = blockIdx.x * 256 + threadIdx.x;
    if (i < NN1) g_deg0[i] = 0;
    else if (i < NN1 + NN2) g_deg1[i - NN1] = 0;
}

// ---------------- padded-CSR fill (both hops fused) ----------------
__global__ void fill_kernel(const int* __restrict__ e0s, const int* __restrict__ e0d,
                            const int* __restrict__ e1s, const int* __restrict__ e1d) {
    int e = blockIdx.x * 256 + threadIdx.x;
    if (e < EE0) {
        int dst = e0d[e];
        int p = atomicAdd(&g_deg0[dst], 1);
        if (p < MAXDEG) ((int*)g_srt0)[(size_t)dst * MAXDEG + p] = e0s[e];
    } else if (e < EE0 + EE1) {
        int i = e - EE0;
        int dst = e1d[i];
        int p = atomicAdd(&g_deg1[dst], 1);
        if (p < MAXDEG) ((int*)g_srt1)[(size_t)dst * MAXDEG + p] = e1s[i];
    }
}

// ---------------- gather-reduce aggregation (mean) ----------------
__device__ __forceinline__ void f4add(float4& a, float4 b) {
    a.x += b.x; a.y += b.y; a.z += b.z; a.w += b.w;
}

// hop 0: D=128 -> one warp per dst, float4 per lane. grid = NN1*32/256 exactly.
__global__ __launch_bounds__(256)
void agg0_kernel(const float4* __restrict__ x4) {
    unsigned gt = blockIdx.x * 256u + threadIdx.x;
    int w = gt >> 5;            // dst node
    int lane = gt & 31;
    int n = min(g_deg0[w], MAXDEG);
    const int4* idx4 = &g_srt0[(size_t)w * (MAXDEG / 4)];
    float4 acc = make_float4(0.f, 0.f, 0.f, 0.f);
    int p = 0;
    for (; p + 4 <= n; p += 4) {
        int4 s = __ldg(idx4 + (p >> 2));   // warp-uniform broadcast
        float4 a = __ldg(&x4[(size_t)s.x * 32 + lane]);
        float4 b = __ldg(&x4[(size_t)s.y * 32 + lane]);
        float4 c = __ldg(&x4[(size_t)s.z * 32 + lane]);
        float4 d = __ldg(&x4[(size_t)s.w * 32 + lane]);
        f4add(acc, a); f4add(acc, b); f4add(acc, c); f4add(acc, d);
    }
    if (p < n) {
        int4 s = __ldg(idx4 + (p >> 2));
        const int rem = n - p;
        f4add(acc, __ldg(&x4[(size_t)s.x * 32 + lane]));
        if (rem > 1) f4add(acc, __ldg(&x4[(size_t)s.y * 32 + lane]));
        if (rem > 2) f4add(acc, __ldg(&x4[(size_t)s.z * 32 + lane]));
    }
    float inv = 1.0f / fmaxf((float)n, 1.0f);
    acc.x *= inv; acc.y *= inv; acc.z *= inv; acc.w *= inv;
    g_agg0[(size_t)w * 32 + lane] = acc;
}

// hop 1: D=256 -> one warp per dst, 2x float4 per lane. grid = NN2*32/256 exactly.
__global__ __launch_bounds__(256)
void agg1_kernel() {
    unsigned gt = blockIdx.x * 256u + threadIdx.x;
    int w = gt >> 5;
    int lane = gt & 31;
    int n = min(g_deg1[w], MAXDEG);
    const int4* idx4 = &g_srt1[(size_t)w * (MAXDEG / 4)];
    float4 acc0 = make_float4(0.f, 0.f, 0.f, 0.f);
    float4 acc1 = make_float4(0.f, 0.f, 0.f, 0.f);
    int p = 0;
    for (; p + 2 <= n; p += 2) {
        int2 s = __ldg((const int2*)idx4 + (p >> 1));
        f4add(acc0, g_h[(size_t)s.x * 64 + lane]);
        f4add(acc1, g_h[(size_t)s.x * 64 + 32 + lane]);
        f4add(acc0, g_h[(size_t)s.y * 64 + lane]);
        f4add(acc1, g_h[(size_t)s.y * 64 + 32 + lane]);
    }
    if (p < n) {
        int s = ((const int*)idx4)[p];
        f4add(acc0, g_h[(size_t)s * 64 + lane]);
        f4add(acc1, g_h[(size_t)s * 64 + 32 + lane]);
    }
    float inv = 1.0f / fmaxf((float)n, 1.0f);
    acc0.x *= inv; acc0.y *= inv; acc0.z *= inv; acc0.w *= inv;
    acc1.x *= inv; acc1.y *= inv; acc1.z *= inv; acc1.w *= inv;
    g_agg1[(size_t)w * 64 + lane] = acc0;
    g_agg1[(size_t)w * 64 + 32 + lane] = acc1;
}

// ---------------- tf32 helpers ----------------
__device__ __forceinline__ uint32_t f2tf32(float f) {
    uint32_t r;
    asm("cvt.rna.tf32.f32 %0, %1;" : "=r"(r) : "f"(f));
    return r;
}
__device__ __forceinline__ void mma_tf32(float* c, const uint32_t* a,
                                         const uint32_t* b) {
    asm volatile(
        "mma.sync.aligned.m16n8k8.row.col.f32.tf32.tf32.f32 "
        "{%0,%1,%2,%3}, {%4,%5,%6,%7}, {%8,%9}, {%0,%1,%2,%3};"
        : "+f"(c[0]), "+f"(c[1]), "+f"(c[2]), "+f"(c[3])
        : "r"(a[0]), "r"(a[1]), "r"(a[2]), "r"(a[3]), "r"(b[0]), "r"(b[1]));
}

// ---------------- fused SAGEConv tf32 mma.sync GEMM (pipelined) ----------------
// out[m,n] = act( sum_k A0[m,k]*B0[n,k] + sum_k A1[m,k]*B1[n,k] + bias[n] )
// Block tile 128x128, BK=32, 256 threads, warp tile 64x32 (m16n8k8).
// Double-buffered dynamic SMEM + register prefetch; one barrier per chunk.
// NOTE: grid is (n_col_tiles, n_row_tiles) — column tiles of the same row
// block are ADJACENT bids so their A reads dedup in L2 within a wave.
template<int KHALF, int N, int DO_RELU>
__global__ __launch_bounds__(256)
void sage_mma_gemm(const float* __restrict__ A0,
                   const float* __restrict__ A1,
                   const float* __restrict__ B0, const float* __restrict__ B1,
                   const float* __restrict__ bias,
                   float* __restrict__ out, int M) {
    constexpr int BK = 32;
    constexpr int LDS_W = BK + 4;
    constexpr int CH = KHALF / BK;
    constexpr int NC = 2 * CH;

    extern __shared__ uint32_t sm[];
    uint32_t (*As)[128][LDS_W] = (uint32_t (*)[128][LDS_W])sm;
    uint32_t (*Bs)[128][LDS_W] = (uint32_t (*)[128][LDS_W])(sm + 2 * 128 * LDS_W);

    const int tid = threadIdx.x;
    const int wid = tid >> 5;
    const int lane = tid & 31;
    const int lrow = lane >> 2;
    const int lcol = lane & 3;
    const int warp_m = (wid >> 2) * 64;
    const int warp_n = (wid & 3) * 32;
    const int row0 = blockIdx.y * 128;   // row tile on y
    const int col0 = blockIdx.x * 128;   // col tile on x (adjacent bids)

    float acc[4][4][4];
#pragma unroll
    for (int mi = 0; mi < 4; ++mi)
#pragma unroll
        for (int ni = 0; ni < 4; ++ni)
#pragma unroll
            for (int j = 0; j < 4; ++j) acc[mi][ni][j] = 0.f;

    float4 pa[4], pb[4];

    auto ldg_chunk = [&](int c) {
        const float* __restrict__ A = (c < CH) ? A0 : A1;
        const float* __restrict__ B = (c < CH) ? B0 : B1;
        const int kb = ((c < CH) ? c : c - CH) * BK;
#pragma unroll
        for (int t = 0; t < 4; ++t) {
            int i = tid + t * 256;
            int r = i >> 3;
            int c4 = (i & 7) * 4;
            int row = row0 + r;
            pa[t] = make_float4(0.f, 0.f, 0.f, 0.f);
            if (row < M)
                pa[t] = *(const float4*)(A + (size_t)row * KHALF + kb + c4);
            pb[t] = *(const float4*)(B + (size_t)(col0 + r) * KHALF + kb + c4);
        }
    };
    auto sts_chunk = [&](int buf) {
#pragma unroll
        for (int t = 0; t < 4; ++t) {
            int i = tid + t * 256;
            int r = i >> 3;
            int c4 = (i & 7) * 4;
            As[buf][r][c4 + 0] = f2tf32(pa[t].x);
            As[buf][r][c4 + 1] = f2tf32(pa[t].y);
            As[buf][r][c4 + 2] = f2tf32(pa[t].z);
            As[buf][r][c4 + 3] = f2tf32(pa[t].w);
            Bs[buf][r][c4 + 0] = f2tf32(pb[t].x);
            Bs[buf][r][c4 + 1] = f2tf32(pb[t].y);
            Bs[buf][r][c4 + 2] = f2tf32(pb[t].z);
            Bs[buf][r][c4 + 3] = f2tf32(pb[t].w);
        }
    };

    ldg_chunk(0);
    sts_chunk(0);
    __syncthreads();

#pragma unroll 1
    for (int c = 0; c < NC; ++c) {
        const int buf = c & 1;
        const bool more = (c + 1 < NC);
        if (more) ldg_chunk(c + 1);
#pragma unroll
        for (int kk = 0; kk < 4; ++kk) {
            const int kof = kk * 8;
            uint32_t af[4][4], bf[4][2];
#pragma unroll
            for (int mi = 0; mi < 4; ++mi) {
                int m = warp_m + mi * 16 + lrow;
                af[mi][0] = As[buf][m][kof + lcol];
                af[mi][1] = As[buf][m + 8][kof + lcol];
                af[mi][2] = As[buf][m][kof + lcol + 4];
                af[mi][3] = As[buf][m + 8][kof + lcol + 4];
            }
#pragma unroll
            for (int ni = 0; ni < 4; ++ni) {
                int n = warp_n + ni * 8 + lrow;
                bf[ni][0] = Bs[buf][n][kof + lcol];
                bf[ni][1] = Bs[buf][n][kof + lcol + 4];
            }
#pragma unroll
            for (int mi = 0; mi < 4; ++mi)
#pragma unroll
                for (int ni = 0; ni < 4; ++ni)
                    mma_tf32(acc[mi][ni], af[mi], bf[ni]);
        }
        if (more) {
            sts_chunk(buf ^ 1);
            __syncthreads();
        }
    }

#pragma unroll
    for (int mi = 0; mi < 4; ++mi) {
        int r_lo = row0 + warp_m + mi * 16 + lrow;
        int r_hi = r_lo + 8;
#pragma unroll
        for (int ni = 0; ni < 4; ++ni) {
            int c = col0 + warp_n + ni * 8 + 2 * lcol;
            float bx = __ldg(bias + c);
            float by = __ldg(bias + c + 1);
            if (r_lo < M) {
                float2 v = make_float2(acc[mi][ni][0] + bx, acc[mi][ni][1] + by);
                if (DO_RELU) { v.x = fmaxf(v.x, 0.f); v.y = fmaxf(v.y, 0.f); }
                *(float2*)(out + (size_t)r_lo * N + c) = v;
            }
            if (r_hi < M) {
                float2 v = make_float2(acc[mi][ni][2] + bx, acc[mi][ni][3] + by);
                if (DO_RELU) { v.x = fmaxf(v.x, 0.f); v.y = fmaxf(v.y, 0.f); }
                *(float2*)(out + (size_t)r_hi * N + c) = v;
            }
        }
    }
}

#define GEMM_SMEM (4 * 128 * 36 * 4)   // 73728 bytes

// ---------------- host launcher ----------------
extern "C" void kernel_launch(void* const* d_in, const int* in_sizes, int n_in,
                              void* d_out, int out_size) {
    const float* x   = (const float*)d_in[0];
    const float* Wl0 = (const float*)d_in[1];
    const float* bl0 = (const float*)d_in[2];
    const float* Wr0 = (const float*)d_in[3];
    const float* Wl1 = (const float*)d_in[4];
    const float* bl1 = (const float*)d_in[5];
    const float* Wr1 = (const float*)d_in[6];
    const int* e0s = (const int*)d_in[7];
    const int* e0d = (const int*)d_in[8];
    const int* e1s = (const int*)d_in[9];
    const int* e1d = (const int*)d_in[10];
    float* out = (float*)d_out;

    void *p_agg0, *p_h, *p_agg1;
    cudaGetSymbolAddress(&p_agg0, g_agg0);
    cudaGetSymbolAddress(&p_h,    g_h);
    cudaGetSymbolAddress(&p_agg1, g_agg1);

    cudaFuncSetAttribute(sage_mma_gemm<DIN, DH, 1>,
                         cudaFuncAttributeMaxDynamicSharedMemorySize, GEMM_SMEM);
    cudaFuncSetAttribute(sage_mma_gemm<DH, DOUT, 0>,
                         cudaFuncAttributeMaxDynamicSharedMemorySize, GEMM_SMEM);

    // 1. zero degree counters
    zero_deg_kernel<<<(NN1 + NN2 + 255) / 256, 256>>>();

    // 2. build padded CSR for both hops (fused)
    fill_kernel<<<(EE0 + EE1 + 255) / 256, 256>>>(e0s, e0d, e1s, e1d);

    // 3. hop-0 aggregate (mean)
    agg0_kernel<<<NN1 * 32 / 256, 256>>>((const float4*)x);

    // 4. hop-0 dense: h = relu([agg0 | x[:N1]] @ [Wl0|Wr0]^T + b)
    {
        dim3 grid(DH / 128, (NN1 + 127) / 128);   // col tiles adjacent
        sage_mma_gemm<DIN, DH, 1><<<grid, 256, GEMM_SMEM>>>(
            (const float*)p_agg0, x, Wl0, Wr0, bl0, (float*)p_h, NN1);
    }

    // 5. hop-1 aggregate (mean)
    agg1_kernel<<<NN2 * 32 / 256, 256>>>();

    // 6. hop-1 dense: out = [agg1 | h[:N2]] @ [Wl1|Wr1]^T + b
    {
        dim3 grid(DOUT / 128, (NN2 + 127) / 128);
        sage_mma_gemm<DH, DOUT, 0><<<grid, 256, GEMM_SMEM>>>(
            (const float*)p_agg1, (const float*)p_h, Wl1, Wr1, bl1, out, NN2);
    }
    (void)in_sizes; (void)n_in; (void)out_size;
}

// round 16
// speedup vs baseline: 1.0511x; 1.0200x over previous
#include <cuda_runtime.h>
#include <cstdint>

// Problem sizes (fixed by reference_code)
#define NN0 500000
#define NN1 100000
#define NN2 25000
#define EE0 1600000
#define EE1 400000
#define DIN 128
#define DH  256
#define DOUT 128
#define MAXDEG 64

// ---------------- device scratch (no allocations allowed) ----------------
__device__ float4 g_agg0[(size_t)NN1 * DIN / 4];   // 51.2 MB
__device__ float4 g_h   [(size_t)NN1 * DH / 4];    // 102.4 MB
__device__ float4 g_agg1[(size_t)NN2 * DH / 4];    // 25.6 MB
__device__ int    g_deg0[NN1];
__device__ int    g_deg1[NN2];
__device__ int4   g_srt0[(size_t)NN1 * MAXDEG / 4];  // 25.6 MB
__device__ int4   g_srt1[(size_t)NN2 * MAXDEG / 4];  // 6.4 MB

// ---------------- zero degree counters ----------------
__global__ void zero_deg_kernel() {
    int i = blockIdx.x * 256 + threadIdx.x;
    if (i < NN1) g_deg0[i] = 0;
    else if (i < NN1 + NN2) g_deg1[i - NN1] = 0;
}

// ---------------- padded-CSR fill (both hops fused) ----------------
__global__ void fill_kernel(const int* __restrict__ e0s, const int* __restrict__ e0d,
                            const int* __restrict__ e1s, const int* __restrict__ e1d) {
    int e = blockIdx.x * 256 + threadIdx.x;
    if (e < EE0) {
        int dst = e0d[e];
        int p = atomicAdd(&g_deg0[dst], 1);
        if (p < MAXDEG) ((int*)g_srt0)[(size_t)dst * MAXDEG + p] = e0s[e];
    } else if (e < EE0 + EE1) {
        int i = e - EE0;
        int dst = e1d[i];
        int p = atomicAdd(&g_deg1[dst], 1);
        if (p < MAXDEG) ((int*)g_srt1)[(size_t)dst * MAXDEG + p] = e1s[i];
    }
}

// ---------------- gather-reduce aggregation (mean) ----------------
__device__ __forceinline__ void f4add(float4& a, float4 b) {
    a.x += b.x; a.y += b.y; a.z += b.z; a.w += b.w;
}

// hop 0: D=128 -> one warp per dst, float4 per lane. grid = NN1*32/256 exactly.
__global__ __launch_bounds__(256)
void agg0_kernel(const float4* __restrict__ x4) {
    unsigned gt = blockIdx.x * 256u + threadIdx.x;
    int w = gt >> 5;            // dst node
    int lane = gt & 31;
    int n = min(g_deg0[w], MAXDEG);
    const int4* idx4 = &g_srt0[(size_t)w * (MAXDEG / 4)];
    float4 acc = make_float4(0.f, 0.f, 0.f, 0.f);
    int p = 0;
    for (; p + 4 <= n; p += 4) {
        int4 s = __ldg(idx4 + (p >> 2));   // warp-uniform broadcast
        float4 a = __ldg(&x4[(size_t)s.x * 32 + lane]);
        float4 b = __ldg(&x4[(size_t)s.y * 32 + lane]);
        float4 c = __ldg(&x4[(size_t)s.z * 32 + lane]);
        float4 d = __ldg(&x4[(size_t)s.w * 32 + lane]);
        f4add(acc, a); f4add(acc, b); f4add(acc, c); f4add(acc, d);
    }
    if (p < n) {
        int4 s = __ldg(idx4 + (p >> 2));
        const int rem = n - p;
        f4add(acc, __ldg(&x4[(size_t)s.x * 32 + lane]));
        if (rem > 1) f4add(acc, __ldg(&x4[(size_t)s.y * 32 + lane]));
        if (rem > 2) f4add(acc, __ldg(&x4[(size_t)s.z * 32 + lane]));
    }
    float inv = 1.0f / fmaxf((float)n, 1.0f);
    acc.x *= inv; acc.y *= inv; acc.z *= inv; acc.w *= inv;
    g_agg0[(size_t)w * 32 + lane] = acc;
}

// hop 1: D=256 -> one warp per dst, 2x float4 per lane. grid = NN2*32/256 exactly.
__global__ __launch_bounds__(256)
void agg1_kernel() {
    unsigned gt = blockIdx.x * 256u + threadIdx.x;
    int w = gt >> 5;
    int lane = gt & 31;
    int n = min(g_deg1[w], MAXDEG);
    const int4* idx4 = &g_srt1[(size_t)w * (MAXDEG / 4)];
    float4 acc0 = make_float4(0.f, 0.f, 0.f, 0.f);
    float4 acc1 = make_float4(0.f, 0.f, 0.f, 0.f);
    int p = 0;
    for (; p + 2 <= n; p += 2) {
        int2 s = __ldg((const int2*)idx4 + (p >> 1));
        f4add(acc0, g_h[(size_t)s.x * 64 + lane]);
        f4add(acc1, g_h[(size_t)s.x * 64 + 32 + lane]);
        f4add(acc0, g_h[(size_t)s.y * 64 + lane]);
        f4add(acc1, g_h[(size_t)s.y * 64 + 32 + lane]);
    }
    if (p < n) {
        int s = ((const int*)idx4)[p];
        f4add(acc0, g_h[(size_t)s * 64 + lane]);
        f4add(acc1, g_h[(size_t)s * 64 + 32 + lane]);
    }
    float inv = 1.0f / fmaxf((float)n, 1.0f);
    acc0.x *= inv; acc0.y *= inv; acc0.z *= inv; acc0.w *= inv;
    acc1.x *= inv; acc1.y *= inv; acc1.z *= inv; acc1.w *= inv;
    g_agg1[(size_t)w * 64 + lane] = acc0;
    g_agg1[(size_t)w * 64 + 32 + lane] = acc1;
}

// ---------------- tf32 helpers ----------------
__device__ __forceinline__ uint32_t f2tf32(float f) {
    uint32_t r;
    asm("cvt.rna.tf32.f32 %0, %1;" : "=r"(r) : "f"(f));
    return r;
}
__device__ __forceinline__ void mma_tf32(float* c, const uint32_t* a,
                                         const uint32_t* b) {
    asm volatile(
        "mma.sync.aligned.m16n8k8.row.col.f32.tf32.tf32.f32 "
        "{%0,%1,%2,%3}, {%4,%5,%6,%7}, {%8,%9}, {%0,%1,%2,%3};"
        : "+f"(c[0]), "+f"(c[1]), "+f"(c[2]), "+f"(c[3])
        : "r"(a[0]), "r"(a[1]), "r"(a[2]), "r"(a[3]), "r"(b[0]), "r"(b[1]));
}

// ---------------- fused SAGEConv tf32 GEMM (2 CTA/SM) ----------------
// out[m,n] = act( sum_k A0[m,k]*B0[n,k] + sum_k A1[m,k]*B1[n,k] + bias[n] )
// Block tile 128x128, BK=32, 256 threads, warp tile 64x32 (m16n8k8 tf32).
// A: register prefetch + cvt at STS (tf32 in SMEM).
// B: cp.async.cg raw fp32 to SMEM, cvt at fragment load (frees 16 regs so
//    2 CTAs/SM fit). One barrier per chunk.
template<int KHALF, int N, int DO_RELU>
__global__ __launch_bounds__(256, 2)
void sage_mma_gemm(const float* __restrict__ A0,
                   const float* __restrict__ A1,
                   const float* __restrict__ B0, const float* __restrict__ B1,
                   const float* __restrict__ bias,
                   float* __restrict__ out, int M) {
    constexpr int BK = 32;
    constexpr int LDS_W = BK + 4;
    constexpr int CH = KHALF / BK;
    constexpr int NC = 2 * CH;

    extern __shared__ uint32_t sm[];
    uint32_t (*As)[128][LDS_W] = (uint32_t (*)[128][LDS_W])sm;   // tf32
    float    (*Bs)[128][LDS_W] = (float (*)[128][LDS_W])(sm + 2 * 128 * LDS_W); // fp32

    const int tid = threadIdx.x;
    const int wid = tid >> 5;
    const int lane = tid & 31;
    const int lrow = lane >> 2;
    const int lcol = lane & 3;
    const int warp_m = (wid >> 2) * 64;
    const int warp_n = (wid & 3) * 32;
    const int row0 = blockIdx.y * 128;   // row tile on y
    const int col0 = blockIdx.x * 128;   // col tile on x (adjacent bids)

    float acc[4][4][4];
#pragma unroll
    for (int mi = 0; mi < 4; ++mi)
#pragma unroll
        for (int ni = 0; ni < 4; ++ni)
#pragma unroll
            for (int j = 0; j < 4; ++j) acc[mi][ni][j] = 0.f;

    float4 pa[4];

    // B chunk via cp.async (raw fp32), one commit group per chunk
    auto issue_b = [&](int c) {
        const float* __restrict__ B = (c < CH) ? B0 : B1;
        const int kb = ((c < CH) ? c : c - CH) * BK;
        const int buf = c & 1;
#pragma unroll
        for (int t = 0; t < 4; ++t) {
            int i = tid + t * 256;
            int r = i >> 3;
            int c4 = (i & 7) * 4;
            uint32_t db = (uint32_t)__cvta_generic_to_shared(&Bs[buf][r][c4]);
            asm volatile("cp.async.cg.shared.global [%0], [%1], 16;"
                         :: "r"(db),
                            "l"(B + (size_t)(col0 + r) * KHALF + kb + c4));
        }
        asm volatile("cp.async.commit_group;");
    };
    // A chunk: LDG into registers
    auto ldg_a = [&](int c) {
        const float* __restrict__ A = (c < CH) ? A0 : A1;
        const int kb = ((c < CH) ? c : c - CH) * BK;
#pragma unroll
        for (int t = 0; t < 4; ++t) {
            int i = tid + t * 256;
            int r = i >> 3;
            int c4 = (i & 7) * 4;
            int row = row0 + r;
            pa[t] = make_float4(0.f, 0.f, 0.f, 0.f);
            if (row < M)
                pa[t] = *(const float4*)(A + (size_t)row * KHALF + kb + c4);
        }
    };
    auto sts_a = [&](int buf) {
#pragma unroll
        for (int t = 0; t < 4; ++t) {
            int i = tid + t * 256;
            int r = i >> 3;
            int c4 = (i & 7) * 4;
            As[buf][r][c4 + 0] = f2tf32(pa[t].x);
            As[buf][r][c4 + 1] = f2tf32(pa[t].y);
            As[buf][r][c4 + 2] = f2tf32(pa[t].z);
            As[buf][r][c4 + 3] = f2tf32(pa[t].w);
        }
    };

    // prologue
    issue_b(0);
    ldg_a(0);
    sts_a(0);
    asm volatile("cp.async.wait_group 0;");
    __syncthreads();

#pragma unroll 1
    for (int c = 0; c < NC; ++c) {
        const int buf = c & 1;
        const bool more = (c + 1 < NC);
        if (more) {
            issue_b(c + 1);     // async copy overlaps compute below
            ldg_a(c + 1);       // LDG latency overlaps compute below
        }
        // --- compute chunk c: 4 k-steps of m16n8k8 ---
#pragma unroll
        for (int kk = 0; kk < 4; ++kk) {
            const int kof = kk * 8;
            uint32_t af[4][4], bf[4][2];
#pragma unroll
            for (int mi = 0; mi < 4; ++mi) {
                int m = warp_m + mi * 16 + lrow;
                af[mi][0] = As[buf][m][kof + lcol];
                af[mi][1] = As[buf][m + 8][kof + lcol];
                af[mi][2] = As[buf][m][kof + lcol + 4];
                af[mi][3] = As[buf][m + 8][kof + lcol + 4];
            }
#pragma unroll
            for (int ni = 0; ni < 4; ++ni) {
                int n = warp_n + ni * 8 + lrow;
                bf[ni][0] = f2tf32(Bs[buf][n][kof + lcol]);
                bf[ni][1] = f2tf32(Bs[buf][n][kof + lcol + 4]);
            }
#pragma unroll
            for (int mi = 0; mi < 4; ++mi)
#pragma unroll
                for (int ni = 0; ni < 4; ++ni)
                    mma_tf32(acc[mi][ni], af[mi], bf[ni]);
        }
        if (more) {
            sts_a(buf ^ 1);
            asm volatile("cp.async.wait_group 0;");
            __syncthreads();
        }
    }

    // --- epilogue: bias + optional relu ---
#pragma unroll
    for (int mi = 0; mi < 4; ++mi) {
        int r_lo = row0 + warp_m + mi * 16 + lrow;
        int r_hi = r_lo + 8;
#pragma unroll
        for (int ni = 0; ni < 4; ++ni) {
            int c = col0 + warp_n + ni * 8 + 2 * lcol;
            float bx = __ldg(bias + c);
            float by = __ldg(bias + c + 1);
            if (r_lo < M) {
                float2 v = make_float2(acc[mi][ni][0] + bx, acc[mi][ni][1] + by);
                if (DO_RELU) { v.x = fmaxf(v.x, 0.f); v.y = fmaxf(v.y, 0.f); }
                *(float2*)(out + (size_t)r_lo * N + c) = v;
            }
            if (r_hi < M) {
                float2 v = make_float2(acc[mi][ni][2] + bx, acc[mi][ni][3] + by);
                if (DO_RELU) { v.x = fmaxf(v.x, 0.f); v.y = fmaxf(v.y, 0.f); }
                *(float2*)(out + (size_t)r_hi * N + c) = v;
            }
        }
    }
}

#define GEMM_SMEM (4 * 128 * 36 * 4)   // 73728 bytes

// ---------------- host launcher ----------------
extern "C" void kernel_launch(void* const* d_in, const int* in_sizes, int n_in,
                              void* d_out, int out_size) {
    const float* x   = (const float*)d_in[0];
    const float* Wl0 = (const float*)d_in[1];
    const float* bl0 = (const float*)d_in[2];
    const float* Wr0 = (const float*)d_in[3];
    const float* Wl1 = (const float*)d_in[4];
    const float* bl1 = (const float*)d_in[5];
    const float* Wr1 = (const float*)d_in[6];
    const int* e0s = (const int*)d_in[7];
    const int* e0d = (const int*)d_in[8];
    const int* e1s = (const int*)d_in[9];
    const int* e1d = (const int*)d_in[10];
    float* out = (float*)d_out;

    void *p_agg0, *p_h, *p_agg1;
    cudaGetSymbolAddress(&p_agg0, g_agg0);
    cudaGetSymbolAddress(&p_h,    g_h);
    cudaGetSymbolAddress(&p_agg1, g_agg1);

    cudaFuncSetAttribute(sage_mma_gemm<DIN, DH, 1>,
                         cudaFuncAttributeMaxDynamicSharedMemorySize, GEMM_SMEM);
    cudaFuncSetAttribute(sage_mma_gemm<DH, DOUT, 0>,
                         cudaFuncAttributeMaxDynamicSharedMemorySize, GEMM_SMEM);

    // 1. zero degree counters
    zero_deg_kernel<<<(NN1 + NN2 + 255) / 256, 256>>>();

    // 2. build padded CSR for both hops (fused)
    fill_kernel<<<(EE0 + EE1 + 255) / 256, 256>>>(e0s, e0d, e1s, e1d);

    // 3. hop-0 aggregate (mean)
    agg0_kernel<<<NN1 * 32 / 256, 256>>>((const float4*)x);

    // 4. hop-0 dense: h = relu([agg0 | x[:N1]] @ [Wl0|Wr0]^T + b)
    {
        dim3 grid(DH / 128, (NN1 + 127) / 128);   // col tiles adjacent
        sage_mma_gemm<DIN, DH, 1><<<grid, 256, GEMM_SMEM>>>(
            (const float*)p_agg0, x, Wl0, Wr0, bl0, (float*)p_h, NN1);
    }

    // 5. hop-1 aggregate (mean)
    agg1_kernel<<<NN2 * 32 / 256, 256>>>();

    // 6. hop-1 dense: out = [agg1 | h[:N2]] @ [Wl1|Wr1]^T + b
    {
        dim3 grid(DOUT / 128, (NN2 + 127) / 128);
        sage_mma_gemm<DH, DOUT, 0><<<grid, 256, GEMM_SMEM>>>(
            (const float*)p_agg1, (const float*)p_h, Wl1, Wr1, bl1, out, NN2);
    }
    (void)in_sizes; (void)n_in; (void)out_size;
}